// round 16
// baseline (speedup 1.0000x reference)
#include <cuda_runtime.h>
#include <math.h>

#define BB   128
#define TSEQ 128
#define DIN  128
#define HID  512
#define MWIN 32
#define NG   5
#define NA   3584
#define NB   2560

#define OFF_XS    0ull
#define SZ_XS     (16384ull*512ull)
#define OFF_XG    (OFF_XS + SZ_XS)
#define SZ_XG     (16384ull*2560ull)
#define OFF_GP    (OFF_XG + SZ_XG)
#define SZ_GP     (16384ull*512ull)
#define OFF_WA    (OFF_GP + SZ_GP)
#define SZ_WA     (512ull*3584ull)
#define OFF_WB    (OFF_WA + SZ_WA)
#define SZ_WB     (512ull*2560ull)
#define OFF_WD    (OFF_WB + SZ_WB)
#define SZ_WD     (1024ull*512ull)
#define OFF_WXG   (OFF_WD + SZ_WD)
#define SZ_WXG    (128ull*2560ull)
#define OFF_PREA  (OFF_WXG + SZ_WXG)
#define SZ_PREA   (128ull*2560ull)
#define OFF_PREB  (OFF_PREA + SZ_PREA)
#define SZ_PREB   (2ull*128ull*2560ull)
#define OFF_QS    (OFF_PREB + SZ_PREB)
#define SZ_QS     (8ull*128ull*512ull)
#define OFF_HS    (OFF_QS + SZ_QS)
#define SZ_HS     (8ull*128ull*512ull)
#define OFF_S     (OFF_HS + SZ_HS)
#define SZ_S      (128ull*512ull)
#define OFF_H     (OFF_S + SZ_S)
#define SZ_H      (128ull*512ull)
#define OFF_C     (OFF_H + SZ_H)
#define SZ_C      (128ull*512ull)
#define OFF_HC    (OFF_C + SZ_C)
#define SZ_HC     (128ull*1024ull)
#define OFF_HE    (OFF_HC + SZ_HC)
#define SZ_HE     (128ull*1024ull)
#define OFF_BUF   (OFF_HE + SZ_HE)
#define SZ_BUF    (128ull*32ull*512ull)
#define OFF_P     (OFF_BUF + SZ_BUF)
#define SZ_P      (128ull*32ull*512ull)
#define WS_TOTAL  (OFF_P + SZ_P)

__device__ float g_ws[WS_TOTAL];

// ---------------- FMA-only transcendentals (no MUFU) ----------------
// reciprocal: magic-constant seed + 3 Newton iterations (rel err ~1e-10)
__device__ __forceinline__ float fmarcp(float d) {
    float r = __uint_as_float(0x7ef311c3u - __float_as_uint(d));
    r = r * fmaf(-d, r, 2.0f);
    r = r * fmaf(-d, r, 2.0f);
    r = r * fmaf(-d, r, 2.0f);
    return r;
}
// Eigen-style rational tanh (FMA only, |err| ~1e-6)
__device__ __forceinline__ float ftanh(float x) {
    float xc = fminf(fmaxf(x, -7.90531111f), 7.90531111f);
    float x2 = xc * xc;
    float p = -2.76076847742355e-16f;
    p = fmaf(p, x2, 2.00018790482477e-13f);
    p = fmaf(p, x2, -8.60467152213735e-11f);
    p = fmaf(p, x2, 5.12229709037114e-08f);
    p = fmaf(p, x2, 1.48572235717979e-05f);
    p = fmaf(p, x2, 6.37261928875436e-04f);
    p = fmaf(p, x2, 4.89352455891786e-03f);
    p = p * xc;
    float q = 1.19825839466702e-06f;
    q = fmaf(q, x2, 1.18534705686654e-04f);
    q = fmaf(q, x2, 2.26843463243900e-03f);
    q = fmaf(q, x2, 4.89352518554385e-03f);
    return p * fmarcp(q);
}
__device__ __forceinline__ float fsig(float x) {
    return fmaf(0.5f, ftanh(0.5f * x), 0.5f);
}
__device__ __forceinline__ void pdl_wait() {
#if __CUDA_ARCH__ >= 900
    cudaGridDependencySynchronize();
#endif
}
__device__ __forceinline__ void l2pf(const float* p) {
    asm volatile("prefetch.global.L2 [%0];" :: "l"(p));
}
__device__ __forceinline__ unsigned long long pack2(float x, float y) {
    unsigned long long r;
    asm("mov.b64 %0, {%1, %2};" : "=l"(r) : "f"(x), "f"(y));
    return r;
}
__device__ __forceinline__ void ffma2(unsigned long long& d,
                                      unsigned long long a,
                                      unsigned long long b) {
    asm("fma.rn.f32x2 %0, %1, %2, %0;" : "+l"(d) : "l"(a), "l"(b));
}

#define GK 16

// ---------------- 256-thread FFMA2 GEMM (prologue + C/D) ----------------
template<int EPI>
__global__ void __launch_bounds__(256) gemm_k(
    const float* __restrict__ A, int lda,
    const float* __restrict__ W, int ldw,
    int K,
    float* __restrict__ out, int ldo,
    const float* __restrict__ p1,
    const float* __restrict__ p2,
    const float* __restrict__ p3)
{
    __shared__ __align__(16) float As[2][GK][64];
    __shared__ __align__(16) float Wsm[2][GK][64];

    const int tid = threadIdx.x;
    const int tx  = tid & 15;
    const int ty  = tid >> 4;
    const int n0  = blockIdx.x * 64;
    const int m0  = blockIdx.y * 64;
    const int z   = blockIdx.z;

    const float* Ab = A + (size_t)m0 * lda + (size_t)z * K;
    const float* Wb = W + (size_t)z * K * ldw + n0;

    const int am = tid >> 2;
    const int ak = (tid & 3) << 2;
    const int wk = tid >> 4;
    const int wn = (tid & 15) << 2;

    unsigned long long acc[4][2];
#pragma unroll
    for (int r = 0; r < 4; r++) { acc[r][0] = 0ull; acc[r][1] = 0ull; }

    float4 w0 = *reinterpret_cast<const float4*>(Wb + (size_t)wk * ldw + wn);
    pdl_wait();
    float4 a0 = *reinterpret_cast<const float4*>(Ab + (size_t)am * lda + ak);

    const int ntile = K / GK;
    for (int kt = 0; kt < ntile; kt++) {
        const int buf = kt & 1;
        As[buf][ak + 0][am] = a0.x; As[buf][ak + 1][am] = a0.y;
        As[buf][ak + 2][am] = a0.z; As[buf][ak + 3][am] = a0.w;
        *reinterpret_cast<float4*>(&Wsm[buf][wk][wn]) = w0;
        __syncthreads();
        if (kt + 1 < ntile) {
            const float* Abn = Ab + (kt + 1) * GK;
            const float* Wbn = Wb + (size_t)(kt + 1) * GK * ldw;
            a0 = *reinterpret_cast<const float4*>(Abn + (size_t)am * lda + ak);
            w0 = *reinterpret_cast<const float4*>(Wbn + (size_t)wk * ldw + wn);
        }
#pragma unroll
        for (int k = 0; k < GK; k++) {
            float4 av = *reinterpret_cast<const float4*>(&As[buf][k][ty * 4]);
            ulonglong2 wv = *reinterpret_cast<const ulonglong2*>(&Wsm[buf][k][tx * 4]);
            unsigned long long a2[4];
            a2[0] = pack2(av.x, av.x); a2[1] = pack2(av.y, av.y);
            a2[2] = pack2(av.z, av.z); a2[3] = pack2(av.w, av.w);
#pragma unroll
            for (int r = 0; r < 4; r++) {
                ffma2(acc[r][0], a2[r], wv.x);
                ffma2(acc[r][1], a2[r], wv.y);
            }
        }
    }

    const size_t zoff = (size_t)z * gridDim.y * 64 * ldo;
#pragma unroll
    for (int r = 0; r < 4; r++) {
        int m = m0 + ty * 4 + r;
#pragma unroll
        for (int j = 0; j < 2; j++) {
            float2 vp = *reinterpret_cast<float2*>(&acc[r][j]);
#pragma unroll
            for (int half = 0; half < 2; half++) {
                int n = n0 + tx * 4 + j * 2 + half;
                float v = half ? vp.y : vp.x;
                if (EPI == 0) {
                    out[zoff + (size_t)m * ldo + n] = v;
                } else if (EPI == 1) {
                    out[(size_t)m * ldo + n] = v + p1[n];
                } else {
                    out[(size_t)m * ldo + n] = v + p3[m] * p2[n] + p1[n];
                }
            }
        }
    }
}

// ---------------- 512-thread GEMM with intra-block K split (A + B) ----------------
template<int EPI>
__global__ void __launch_bounds__(512) gemm2_k(
    const float* __restrict__ A, int lda,
    const float* __restrict__ W, int ldw,
    int K,
    float* __restrict__ out, int ldo,
    const float* __restrict__ p1,
    float* __restrict__ q1, float* __restrict__ q2, float* __restrict__ q3)
{
    __shared__ __align__(16) float smem[2][2][2][GK][64];

    const int tid  = threadIdx.x;
    const int half = tid >> 8;
    const int ht   = tid & 255;
    const int tx   = ht & 15;
    const int ty   = ht >> 4;
    const int n0   = blockIdx.x * 64;
    const int m0   = blockIdx.y * 64;
    const int z    = blockIdx.z;

    const int K2 = K >> 1;
    const float* Ab = A + (size_t)m0 * lda + (size_t)z * K + (size_t)half * K2;
    const float* Wb = W + ((size_t)z * K + (size_t)half * K2) * ldw + n0;

    float (*As)[GK][64]  = smem[half][0];
    float (*Wsm)[GK][64] = smem[half][1];

    const int am = ht >> 2;
    const int ak = (ht & 3) << 2;
    const int wk = ht >> 4;
    const int wn = (ht & 15) << 2;

    unsigned long long acc[4][2];
#pragma unroll
    for (int r = 0; r < 4; r++) { acc[r][0] = 0ull; acc[r][1] = 0ull; }

    float4 w0 = *reinterpret_cast<const float4*>(Wb + (size_t)wk * ldw + wn);
    pdl_wait();
    float4 a0 = *reinterpret_cast<const float4*>(Ab + (size_t)am * lda + ak);

    const int ntile = K2 / GK;
    for (int kt = 0; kt < ntile; kt++) {
        const int buf = kt & 1;
        As[buf][ak + 0][am] = a0.x; As[buf][ak + 1][am] = a0.y;
        As[buf][ak + 2][am] = a0.z; As[buf][ak + 3][am] = a0.w;
        *reinterpret_cast<float4*>(&Wsm[buf][wk][wn]) = w0;
        __syncthreads();
        if (kt + 1 < ntile) {
            const float* Abn = Ab + (kt + 1) * GK;
            const float* Wbn = Wb + (size_t)(kt + 1) * GK * ldw;
            a0 = *reinterpret_cast<const float4*>(Abn + (size_t)am * lda + ak);
            w0 = *reinterpret_cast<const float4*>(Wbn + (size_t)wk * ldw + wn);
        }
#pragma unroll
        for (int k = 0; k < GK; k++) {
            float4 av = *reinterpret_cast<const float4*>(&As[buf][k][ty * 4]);
            ulonglong2 wv = *reinterpret_cast<const ulonglong2*>(&Wsm[buf][k][tx * 4]);
            unsigned long long a2[4];
            a2[0] = pack2(av.x, av.x); a2[1] = pack2(av.y, av.y);
            a2[2] = pack2(av.z, av.z); a2[3] = pack2(av.w, av.w);
#pragma unroll
            for (int r = 0; r < 4; r++) {
                ffma2(acc[r][0], a2[r], wv.x);
                ffma2(acc[r][1], a2[r], wv.y);
            }
        }
    }
    __syncthreads();

    float2* exch = reinterpret_cast<float2*>(smem[1]);
    if (half == 1) {
#pragma unroll
        for (int r = 0; r < 4; r++)
#pragma unroll
            for (int j = 0; j < 2; j++)
                exch[(ty * 4 + r) * 32 + tx * 2 + j] =
                    *reinterpret_cast<float2*>(&acc[r][j]);
    }
    __syncthreads();
    if (half == 1) return;

    const size_t zoff = (size_t)z * gridDim.y * 64 * (EPI == 3 ? 0 : ldo);
#pragma unroll
    for (int r = 0; r < 4; r++) {
        int m = m0 + ty * 4 + r;
#pragma unroll
        for (int j = 0; j < 2; j++) {
            float2 vp = *reinterpret_cast<float2*>(&acc[r][j]);
            float2 ev = exch[(ty * 4 + r) * 32 + tx * 2 + j];
            vp.x += ev.x; vp.y += ev.y;
#pragma unroll
            for (int hb = 0; hb < 2; hb++) {
                int n = n0 + tx * 4 + j * 2 + hb;
                float v = hb ? vp.y : vp.x;
                if (EPI == 0) {
                    out[zoff + (size_t)m * ldo + n] = v;
                } else { // EPI == 3
                    if (n0 < 512) {
                        q1[(size_t)m * 512 + n] = ftanh(v + p1[(size_t)m * (TSEQ * HID) + n]);
                    } else if (n0 < 3072) {
                        q2[(size_t)m * 2560 + (n - 512)] = v;
                    } else {
                        q3[(size_t)m * (MWIN * HID) + (n - 3072)] = v;
                    }
                }
            }
        }
    }
}

// ---------------- pack kernels ----------------
__global__ void packA_k(const float* __restrict__ Wsh, const float* __restrict__ Wh,
                        const float* __restrict__ Wah)
{
    pdl_wait();
    int idx = blockIdx.x * 256 + threadIdx.x;
    int k = idx / NA, n = idx % NA;
    float v;
    if (n < 512) v = Wsh[k * 512 + n];
    else if (n < 3072) {
        int g = (n - 512) >> 9, h = (n - 512) & 511;
        v = Wh[(size_t)g * 262144 + k * 512 + h];
    } else v = Wah[k * 512 + (n - 3072)];
    g_ws[OFF_WA + idx] = v;
}
__global__ void packB_k(const float* __restrict__ Ws5)
{
    pdl_wait();
    int idx = blockIdx.x * 256 + threadIdx.x;
    int k = idx / NB, n = idx % NB;
    g_ws[OFF_WB + idx] = Ws5[(size_t)(n >> 9) * 262144 + k * 512 + (n & 511)];
}
__global__ void packD_k(const float* __restrict__ W_h, const float* __restrict__ W_e)
{
    pdl_wait();
    int idx = blockIdx.x * 256 + threadIdx.x;
    int k = idx >> 9, n = idx & 511;
    g_ws[OFF_WD + idx] = (k < 512) ? W_h[k * 512 + n] : W_e[(k - 512) * 512 + n];
}
__global__ void packXG_k(const float* __restrict__ Wx5)
{
    pdl_wait();
    int idx = blockIdx.x * 256 + threadIdx.x;
    int d = idx / NB, n = idx % NB;
    g_ws[OFF_WXG + idx] = Wx5[(size_t)(n >> 9) * 65536 + d * 512 + (n & 511)];
}
__global__ void zero_hc_k()
{
    pdl_wait();
    int idx = blockIdx.x * 256 + threadIdx.x;
    if (idx < 65536) g_ws[OFF_H + idx] = 0.0f;
    else             g_ws[OFF_C + (idx - 65536)] = 0.0f;
}

// ---------------- cell kernel ----------------
__global__ void __launch_bounds__(256) cell_k(const float* __restrict__ XG_t, int t)
{
    int idx = blockIdx.x * 256 + threadIdx.x;
    int b = idx >> 9, h = idx & 511;
    float pre[NG];
#pragma unroll
    for (int g = 0; g < NG; g++)
        pre[g] = XG_t[(size_t)b * (TSEQ * 2560) + (size_t)g * 512 + h];
    pdl_wait();
    const float* preA  = g_ws + OFF_PREA;
    const float* preB0 = g_ws + OFF_PREB;
    const float* preB1 = g_ws + OFF_PREB + 128ull * 2560ull;
#pragma unroll
    for (int g = 0; g < NG; g++) {
        size_t col = (size_t)g * 512 + h;
        pre[g] += preA[(size_t)b * 2560 + col] + preB0[(size_t)b * 2560 + col]
                + preB1[(size_t)b * 2560 + col];
    }
    float f  = fsig(pre[0]);
    float i_ = fsig(pre[1]);
    float Tt = fsig(pre[2]);
    float zt = ftanh(pre[3]);
    float o  = fsig(pre[4]);
    float sv = g_ws[OFF_S + idx];
    float cv = f * g_ws[OFF_C + idx] + i_ * zt + Tt * sv;
    g_ws[OFF_C + idx] = cv;
    float ht = o * ftanh(cv);
    g_ws[OFF_HC + (size_t)b * 1024 + h]       = ht;
    g_ws[OFF_HC + (size_t)b * 1024 + 512 + h] = cv;
    g_ws[OFF_HE + (size_t)b * 1024 + h]       = ht;
}

// ---------------- attention kernel (tanh now FMA-only) ----------------
__global__ void __launch_bounds__(256) attn_k(
    const float* __restrict__ ba, const float* __restrict__ vt, int t)
{
    __shared__ float qv[512];
    __shared__ float sc[32];
    __shared__ float al[32];
    int b = blockIdx.x, tid = threadIdx.x;
    float ba0 = ba[tid], ba1 = ba[tid + 256];
    pdl_wait();
    float* he = g_ws + OFF_HE;
    if (t == 0) {
        he[(size_t)b * 1024 + 512 + tid]       = 0.0f;
        he[(size_t)b * 1024 + 512 + 256 + tid] = 0.0f;
        return;
    }
    int nv = (t < MWIN) ? t : MWIN;
    const float* qs  = g_ws + OFF_QS;
    const float* P   = g_ws + OFF_P;
    const float* buf = g_ws + OFF_BUF;
#pragma unroll
    for (int j = 0; j < 2; j++) {
        int h = tid + j * 256;
        float q = j ? ba1 : ba0;
#pragma unroll
        for (int s = 0; s < 8; s++) q += qs[(size_t)s * 65536 + (size_t)b * 512 + h];
        qv[h] = q;
    }
    __syncthreads();
    int wid = tid >> 5, lane = tid & 31;
    for (int mi = wid; mi < nv; mi += 8) {
        int slot = (t - 1 - mi) & 31;
        const float* Pp = P + ((size_t)b * 32 + slot) * 512;
        float ps = 0.0f;
        for (int h = lane; h < 512; h += 32)
            ps = fmaf(vt[h], ftanh(qv[h] + Pp[h]), ps);
#pragma unroll
        for (int o = 16; o; o >>= 1) ps += __shfl_xor_sync(0xffffffffu, ps, o);
        if (lane == 0) sc[mi] = ps;
    }
    __syncthreads();
    if (wid == 0) {
        float s = (lane < nv) ? sc[lane] : -1e30f;
        float mx = s;
#pragma unroll
        for (int o = 16; o; o >>= 1) mx = fmaxf(mx, __shfl_xor_sync(0xffffffffu, mx, o));
        float e = (lane < nv) ? __expf(s - mx) : 0.0f;
        float sum = e;
#pragma unroll
        for (int o = 16; o; o >>= 1) sum += __shfl_xor_sync(0xffffffffu, sum, o);
        al[lane] = __fdividef(e, sum);
    }
    __syncthreads();
#pragma unroll
    for (int j = 0; j < 2; j++) {
        int h = tid + j * 256;
        float e = 0.0f;
        for (int mi = 0; mi < nv; mi++) {
            int slot = (t - 1 - mi) & 31;
            e = fmaf(al[mi], buf[((size_t)b * 32 + slot) * 512 + h], e);
        }
        he[(size_t)b * 1024 + 512 + h] = e;
    }
}

// ---------------- h update + logit + next-step L2 prefetch ----------------
__global__ void __launch_bounds__(512) hout_k(
    const float* __restrict__ GP_t,
    const float* __restrict__ Wcls, const float* __restrict__ bcls,
    float* __restrict__ out, int t,
    const float* __restrict__ xg_next,
    const float* __restrict__ gp_next,
    const float* __restrict__ xs_next)
{
    int b = blockIdx.x, h = threadIdx.x;
    float pre = GP_t[(size_t)b * (TSEQ * HID) + h];
    float wc  = Wcls[h];

    if (h < 80)
        l2pf(xg_next + (size_t)b * (TSEQ * 2560) + h * 32);
    else if (h < 96)
        l2pf(gp_next + (size_t)b * (TSEQ * HID) + (h - 80) * 32);
    else if (h < 112)
        l2pf(xs_next + (size_t)b * (TSEQ * HID) + (h - 96) * 32);

    pdl_wait();
    const float* hs = g_ws + OFF_HS;
#pragma unroll
    for (int s = 0; s < 8; s++) pre += hs[(size_t)s * 65536 + (size_t)b * 512 + h];
    float ht = ftanh(pre);
    g_ws[OFF_H + (size_t)b * 512 + h] = ht;
    g_ws[OFF_BUF + ((size_t)b * 32 + (t & 31)) * 512 + h] = ht;

    float p = ht * wc;
#pragma unroll
    for (int o = 16; o; o >>= 1) p += __shfl_xor_sync(0xffffffffu, p, o);
    __shared__ float red[16];
    int wid = h >> 5, lane = h & 31;
    if (lane == 0) red[wid] = p;
    __syncthreads();
    if (wid == 0) {
        float p2 = (lane < 16) ? red[lane] : 0.0f;
#pragma unroll
        for (int o = 8; o; o >>= 1) p2 += __shfl_xor_sync(0xffffffffu, p2, o);
        if (lane == 0) out[(size_t)b * TSEQ + t] = p2 + bcls[0];
    }
}

// ---------------- PDL launch helper ----------------
template<typename Kern, typename... Args>
static inline void pdl(Kern kern, dim3 g, dim3 b, Args... args)
{
    cudaLaunchConfig_t cfg = {};
    cfg.gridDim = g;
    cfg.blockDim = b;
    cfg.dynamicSmemBytes = 0;
    cfg.stream = 0;
    cudaLaunchAttribute at;
    at.id = cudaLaunchAttributeProgrammaticStreamSerialization;
    at.val.programmaticStreamSerializationAllowed = 1;
    cfg.attrs = &at;
    cfg.numAttrs = 1;
    cudaLaunchKernelEx(&cfg, kern, args...);
}

// ---------------- host ----------------
extern "C" void kernel_launch(void* const* d_in, const int* in_sizes, int n_in,
                              void* d_out, int out_size)
{
    const float* x    = (const float*)d_in[0];
    const float* dlt  = (const float*)d_in[1];
    const float* gseq = (const float*)d_in[2];
    const float* Wsh  = (const float*)d_in[3];
    const float* Wsx  = (const float*)d_in[4];
    const float* Wst  = (const float*)d_in[5];
    const float* bs   = (const float*)d_in[6];
    const float* Wh5  = (const float*)d_in[7];
    const float* Wx5  = (const float*)d_in[8];
    const float* Ws5  = (const float*)d_in[9];
    const float* bg   = (const float*)d_in[10];
    const float* Waq  = (const float*)d_in[11];
    const float* Wah  = (const float*)d_in[12];
    const float* ba   = (const float*)d_in[13];
    const float* vt   = (const float*)d_in[14];
    const float* W_h  = (const float*)d_in[15];
    const float* W_e  = (const float*)d_in[16];
    const float* W_g  = (const float*)d_in[17];
    const float* b_h  = (const float*)d_in[18];
    const float* Wcls = (const float*)d_in[19];
    const float* bcls = (const float*)d_in[20];
    float* out = (float*)d_out;

    float* ws = nullptr;
    cudaGetSymbolAddress((void**)&ws, g_ws);

    auto launchA = [&](int t) {
        int slotp = (t + 31) & 31;
        pdl(gemm2_k<3>, dim3(NA / 64, 2, 1), dim3(512),
            (const float*)(ws + OFF_H), HID,
            (const float*)(ws + OFF_WA), NA, HID,
            (float*)nullptr, 0,
            (const float*)(ws + OFF_XS + (size_t)t * HID),
            ws + OFF_S, ws + OFF_PREA, ws + OFF_P + (size_t)slotp * HID);
    };
    auto launchB = [&]() {
        pdl(gemm2_k<0>, dim3(NB / 64, 2, 2), dim3(512),
            (const float*)(ws + OFF_S), HID,
            (const float*)(ws + OFF_WB), NB, HID / 2,
            ws + OFF_PREB, NB,
            (const float*)nullptr, (float*)nullptr, (float*)nullptr, (float*)nullptr);
    };
    auto launchC = [&]() {
        pdl(gemm_k<0>, dim3(HID / 64, 2, 8), dim3(256),
            (const float*)(ws + OFF_HC), 1024, Waq, HID, 1024 / 8,
            ws + OFF_QS, HID,
            (const float*)nullptr, (const float*)nullptr, (const float*)nullptr);
    };
    auto launchD = [&]() {
        pdl(gemm_k<0>, dim3(HID / 64, 2, 8), dim3(256),
            (const float*)(ws + OFF_HE), 1024,
            (const float*)(ws + OFF_WD), HID, 1024 / 8,
            ws + OFF_HS, HID,
            (const float*)nullptr, (const float*)nullptr, (const float*)nullptr);
    };
    auto launchH = [&](int t) {
        int tn = (t + 1 < TSEQ) ? t + 1 : 0;
        pdl(hout_k, dim3(128), dim3(512),
            (const float*)(ws + OFF_GP + (size_t)t * HID), Wcls, bcls, out, t,
            (const float*)(ws + OFF_XG + (size_t)tn * NB),
            (const float*)(ws + OFF_GP + (size_t)tn * HID),
            (const float*)(ws + OFF_XS + (size_t)tn * HID));
    };

    // prologue interleaved with step 0 (ncu -s 5 catches step-0 GEMM A)
    pdl(zero_hc_k, dim3(512), dim3(256));                                    // 1
    pdl(packA_k, dim3((512 * NA) / 256), dim3(256), Wsh, Wh5, Wah);          // 2
    pdl(gemm_k<2>, dim3(8, 256, 1), dim3(256),                               // 3: XS
        x, DIN, Wsx, HID, DIN, ws + OFF_XS, HID, bs, Wst, dlt);
    launchA(0);                                                              // 4
    pdl(packB_k, dim3((512 * NB) / 256), dim3(256), Ws5);                    // 5
    launchB();                                                               // 6
    pdl(packXG_k, dim3((128 * NB) / 256), dim3(256), Wx5);                   // 7
    pdl(gemm_k<1>, dim3(40, 256, 1), dim3(256),                              // 8: XG
        x, DIN, (const float*)(ws + OFF_WXG), NB, DIN,
        ws + OFF_XG, NB, bg, (const float*)nullptr, (const float*)nullptr);
    pdl(cell_k, dim3(256), dim3(256), (const float*)(ws + OFF_XG), 0);       // 9
    launchC();                                                               // 10
    pdl(attn_k, dim3(128), dim3(256), ba, vt, 0);                            // 11
    pdl(packD_k, dim3((1024 * 512) / 256), dim3(256), W_h, W_e);             // 12
    launchD();                                                               // 13
    pdl(gemm_k<1>, dim3(8, 256, 1), dim3(256),                               // 14: GP
        gseq, DIN, W_g, HID, DIN,
        ws + OFF_GP, HID, b_h, (const float*)nullptr, (const float*)nullptr);
    launchH(0);                                                              // 15

    for (int t = 1; t < TSEQ; t++) {
        launchA(t);
        launchB();
        pdl(cell_k, dim3(256), dim3(256),
            (const float*)(ws + OFF_XG + (size_t)t * NB), t);
        launchC();
        pdl(attn_k, dim3(128), dim3(256), ba, vt, t);
        launchD();
        launchH(t);
    }
    (void)in_sizes; (void)n_in; (void)out_size;
}

// round 17
// speedup vs baseline: 1.1968x; 1.1968x over previous
#include <cuda_runtime.h>
#include <math.h>

#define BB   128
#define TSEQ 128
#define DIN  128
#define HID  512
#define MWIN 32
#define NG   5
#define NA   3584
#define NB   2560

#define OFF_XS    0ull
#define SZ_XS     (16384ull*512ull)
#define OFF_XG    (OFF_XS + SZ_XS)
#define SZ_XG     (16384ull*2560ull)
#define OFF_GP    (OFF_XG + SZ_XG)
#define SZ_GP     (16384ull*512ull)
#define OFF_WA    (OFF_GP + SZ_GP)
#define SZ_WA     (512ull*3584ull)
#define OFF_WB    (OFF_WA + SZ_WA)
#define SZ_WB     (512ull*2560ull)
#define OFF_WD    (OFF_WB + SZ_WB)
#define SZ_WD     (1024ull*512ull)
#define OFF_WXG   (OFF_WD + SZ_WD)
#define SZ_WXG    (128ull*2560ull)
#define OFF_PREA  (OFF_WXG + SZ_WXG)
#define SZ_PREA   (128ull*2560ull)
#define OFF_PREB  (OFF_PREA + SZ_PREA)
#define SZ_PREB   (2ull*128ull*2560ull)
#define OFF_QS    (OFF_PREB + SZ_PREB)
#define SZ_QS     (8ull*128ull*512ull)
#define OFF_HS    (OFF_QS + SZ_QS)
#define SZ_HS     (8ull*128ull*512ull)
#define OFF_S     (OFF_HS + SZ_HS)
#define SZ_S      (128ull*512ull)
#define OFF_H     (OFF_S + SZ_S)
#define SZ_H      (128ull*512ull)
#define OFF_C     (OFF_H + SZ_H)
#define SZ_C      (128ull*512ull)
#define OFF_HC    (OFF_C + SZ_C)
#define SZ_HC     (128ull*1024ull)
#define OFF_HE    (OFF_HC + SZ_HC)
#define SZ_HE     (128ull*1024ull)
#define OFF_BUF   (OFF_HE + SZ_HE)
#define SZ_BUF    (128ull*32ull*512ull)
#define OFF_P     (OFF_BUF + SZ_BUF)
#define SZ_P      (128ull*32ull*512ull)
#define WS_TOTAL  (OFF_P + SZ_P)

__device__ float g_ws[WS_TOTAL];

// MUFU-based transcendentals (empirically fastest — R15 FMA version regressed)
__device__ __forceinline__ float ftanh(float x) {
    float e = __expf(2.0f * x);
    return 1.0f - __fdividef(2.0f, e + 1.0f);
}
__device__ __forceinline__ float fsig(float x) {
    return __fdividef(1.0f, 1.0f + __expf(-x));
}
__device__ __forceinline__ void pdl_wait() {
#if __CUDA_ARCH__ >= 900
    cudaGridDependencySynchronize();
#endif
}
__device__ __forceinline__ void l2pf(const float* p) {
    asm volatile("prefetch.global.L2 [%0];" :: "l"(p));
}
__device__ __forceinline__ unsigned long long pack2(float x, float y) {
    unsigned long long r;
    asm("mov.b64 %0, {%1, %2};" : "=l"(r) : "f"(x), "f"(y));
    return r;
}
__device__ __forceinline__ void ffma2(unsigned long long& d,
                                      unsigned long long a,
                                      unsigned long long b) {
    asm("fma.rn.f32x2 %0, %1, %2, %0;" : "+l"(d) : "l"(a), "l"(b));
}

#define GK 16

// ---------------- 256-thread FFMA2 GEMM (prologue + C/D) ----------------
template<int EPI>
__global__ void __launch_bounds__(256) gemm_k(
    const float* __restrict__ A, int lda,
    const float* __restrict__ W, int ldw,
    int K,
    float* __restrict__ out, int ldo,
    const float* __restrict__ p1,
    const float* __restrict__ p2,
    const float* __restrict__ p3)
{
    __shared__ __align__(16) float As[2][GK][64];
    __shared__ __align__(16) float Wsm[2][GK][64];

    const int tid = threadIdx.x;
    const int tx  = tid & 15;
    const int ty  = tid >> 4;
    const int n0  = blockIdx.x * 64;
    const int m0  = blockIdx.y * 64;
    const int z   = blockIdx.z;

    const float* Ab = A + (size_t)m0 * lda + (size_t)z * K;
    const float* Wb = W + (size_t)z * K * ldw + n0;

    const int am = tid >> 2;
    const int ak = (tid & 3) << 2;
    const int wk = tid >> 4;
    const int wn = (tid & 15) << 2;

    unsigned long long acc[4][2];
#pragma unroll
    for (int r = 0; r < 4; r++) { acc[r][0] = 0ull; acc[r][1] = 0ull; }

    float4 w0 = *reinterpret_cast<const float4*>(Wb + (size_t)wk * ldw + wn);
    pdl_wait();
    float4 a0 = *reinterpret_cast<const float4*>(Ab + (size_t)am * lda + ak);

    const int ntile = K / GK;
    for (int kt = 0; kt < ntile; kt++) {
        const int buf = kt & 1;
        As[buf][ak + 0][am] = a0.x; As[buf][ak + 1][am] = a0.y;
        As[buf][ak + 2][am] = a0.z; As[buf][ak + 3][am] = a0.w;
        *reinterpret_cast<float4*>(&Wsm[buf][wk][wn]) = w0;
        __syncthreads();
        if (kt + 1 < ntile) {
            const float* Abn = Ab + (kt + 1) * GK;
            const float* Wbn = Wb + (size_t)(kt + 1) * GK * ldw;
            a0 = *reinterpret_cast<const float4*>(Abn + (size_t)am * lda + ak);
            w0 = *reinterpret_cast<const float4*>(Wbn + (size_t)wk * ldw + wn);
        }
#pragma unroll
        for (int k = 0; k < GK; k++) {
            float4 av = *reinterpret_cast<const float4*>(&As[buf][k][ty * 4]);
            ulonglong2 wv = *reinterpret_cast<const ulonglong2*>(&Wsm[buf][k][tx * 4]);
            unsigned long long a2[4];
            a2[0] = pack2(av.x, av.x); a2[1] = pack2(av.y, av.y);
            a2[2] = pack2(av.z, av.z); a2[3] = pack2(av.w, av.w);
#pragma unroll
            for (int r = 0; r < 4; r++) {
                ffma2(acc[r][0], a2[r], wv.x);
                ffma2(acc[r][1], a2[r], wv.y);
            }
        }
    }

    const size_t zoff = (size_t)z * gridDim.y * 64 * ldo;
#pragma unroll
    for (int r = 0; r < 4; r++) {
        int m = m0 + ty * 4 + r;
#pragma unroll
        for (int j = 0; j < 2; j++) {
            float2 vp = *reinterpret_cast<float2*>(&acc[r][j]);
#pragma unroll
            for (int half = 0; half < 2; half++) {
                int n = n0 + tx * 4 + j * 2 + half;
                float v = half ? vp.y : vp.x;
                if (EPI == 0) {
                    out[zoff + (size_t)m * ldo + n] = v;
                } else if (EPI == 1) {
                    out[(size_t)m * ldo + n] = v + p1[n];
                } else {
                    out[(size_t)m * ldo + n] = v + p3[m] * p2[n] + p1[n];
                }
            }
        }
    }
}

// ---------------- 512-thread GEMM with intra-block K split (A + B) ----------------
template<int EPI>
__global__ void __launch_bounds__(512) gemm2_k(
    const float* __restrict__ A, int lda,
    const float* __restrict__ W, int ldw,
    int K,
    float* __restrict__ out, int ldo,
    const float* __restrict__ p1,
    float* __restrict__ q1, float* __restrict__ q2, float* __restrict__ q3)
{
    __shared__ __align__(16) float smem[2][2][2][GK][64];

    const int tid  = threadIdx.x;
    const int half = tid >> 8;
    const int ht   = tid & 255;
    const int tx   = ht & 15;
    const int ty   = ht >> 4;
    const int n0   = blockIdx.x * 64;
    const int m0   = blockIdx.y * 64;
    const int z    = blockIdx.z;

    const int K2 = K >> 1;
    const float* Ab = A + (size_t)m0 * lda + (size_t)z * K + (size_t)half * K2;
    const float* Wb = W + ((size_t)z * K + (size_t)half * K2) * ldw + n0;

    float (*As)[GK][64]  = smem[half][0];
    float (*Wsm)[GK][64] = smem[half][1];

    const int am = ht >> 2;
    const int ak = (ht & 3) << 2;
    const int wk = ht >> 4;
    const int wn = (ht & 15) << 2;

    unsigned long long acc[4][2];
#pragma unroll
    for (int r = 0; r < 4; r++) { acc[r][0] = 0ull; acc[r][1] = 0ull; }

    float4 w0 = *reinterpret_cast<const float4*>(Wb + (size_t)wk * ldw + wn);
    pdl_wait();
    float4 a0 = *reinterpret_cast<const float4*>(Ab + (size_t)am * lda + ak);

    const int ntile = K2 / GK;
    for (int kt = 0; kt < ntile; kt++) {
        const int buf = kt & 1;
        As[buf][ak + 0][am] = a0.x; As[buf][ak + 1][am] = a0.y;
        As[buf][ak + 2][am] = a0.z; As[buf][ak + 3][am] = a0.w;
        *reinterpret_cast<float4*>(&Wsm[buf][wk][wn]) = w0;
        __syncthreads();
        if (kt + 1 < ntile) {
            const float* Abn = Ab + (kt + 1) * GK;
            const float* Wbn = Wb + (size_t)(kt + 1) * GK * ldw;
            a0 = *reinterpret_cast<const float4*>(Abn + (size_t)am * lda + ak);
            w0 = *reinterpret_cast<const float4*>(Wbn + (size_t)wk * ldw + wn);
        }
#pragma unroll
        for (int k = 0; k < GK; k++) {
            float4 av = *reinterpret_cast<const float4*>(&As[buf][k][ty * 4]);
            ulonglong2 wv = *reinterpret_cast<const ulonglong2*>(&Wsm[buf][k][tx * 4]);
            unsigned long long a2[4];
            a2[0] = pack2(av.x, av.x); a2[1] = pack2(av.y, av.y);
            a2[2] = pack2(av.z, av.z); a2[3] = pack2(av.w, av.w);
#pragma unroll
            for (int r = 0; r < 4; r++) {
                ffma2(acc[r][0], a2[r], wv.x);
                ffma2(acc[r][1], a2[r], wv.y);
            }
        }
    }
    __syncthreads();

    float2* exch = reinterpret_cast<float2*>(smem[1]);
    if (half == 1) {
#pragma unroll
        for (int r = 0; r < 4; r++)
#pragma unroll
            for (int j = 0; j < 2; j++)
                exch[(ty * 4 + r) * 32 + tx * 2 + j] =
                    *reinterpret_cast<float2*>(&acc[r][j]);
    }
    __syncthreads();
    if (half == 1) return;

    const size_t zoff = (size_t)z * gridDim.y * 64 * (EPI == 3 ? 0 : ldo);
#pragma unroll
    for (int r = 0; r < 4; r++) {
        int m = m0 + ty * 4 + r;
#pragma unroll
        for (int j = 0; j < 2; j++) {
            float2 vp = *reinterpret_cast<float2*>(&acc[r][j]);
            float2 ev = exch[(ty * 4 + r) * 32 + tx * 2 + j];
            vp.x += ev.x; vp.y += ev.y;
#pragma unroll
            for (int hb = 0; hb < 2; hb++) {
                int n = n0 + tx * 4 + j * 2 + hb;
                float v = hb ? vp.y : vp.x;
                if (EPI == 0) {
                    out[zoff + (size_t)m * ldo + n] = v;
                } else { // EPI == 3
                    if (n0 < 512) {
                        q1[(size_t)m * 512 + n] = ftanh(v + p1[(size_t)m * (TSEQ * HID) + n]);
                    } else if (n0 < 3072) {
                        q2[(size_t)m * 2560 + (n - 512)] = v;
                    } else {
                        q3[(size_t)m * (MWIN * HID) + (n - 3072)] = v;
                    }
                }
            }
        }
    }
}

// ---------------- pack kernels ----------------
__global__ void packA_k(const float* __restrict__ Wsh, const float* __restrict__ Wh,
                        const float* __restrict__ Wah)
{
    pdl_wait();
    int idx = blockIdx.x * 256 + threadIdx.x;
    int k = idx / NA, n = idx % NA;
    float v;
    if (n < 512) v = Wsh[k * 512 + n];
    else if (n < 3072) {
        int g = (n - 512) >> 9, h = (n - 512) & 511;
        v = Wh[(size_t)g * 262144 + k * 512 + h];
    } else v = Wah[k * 512 + (n - 3072)];
    g_ws[OFF_WA + idx] = v;
}
__global__ void packB_k(const float* __restrict__ Ws5)
{
    pdl_wait();
    int idx = blockIdx.x * 256 + threadIdx.x;
    int k = idx / NB, n = idx % NB;
    g_ws[OFF_WB + idx] = Ws5[(size_t)(n >> 9) * 262144 + k * 512 + (n & 511)];
}
__global__ void packD_k(const float* __restrict__ W_h, const float* __restrict__ W_e)
{
    pdl_wait();
    int idx = blockIdx.x * 256 + threadIdx.x;
    int k = idx >> 9, n = idx & 511;
    g_ws[OFF_WD + idx] = (k < 512) ? W_h[k * 512 + n] : W_e[(k - 512) * 512 + n];
}
__global__ void packXG_k(const float* __restrict__ Wx5)
{
    pdl_wait();
    int idx = blockIdx.x * 256 + threadIdx.x;
    int d = idx / NB, n = idx % NB;
    g_ws[OFF_WXG + idx] = Wx5[(size_t)(n >> 9) * 65536 + d * 512 + (n & 511)];
}
__global__ void zero_hc_k()
{
    pdl_wait();
    int idx = blockIdx.x * 256 + threadIdx.x;
    if (idx < 65536) g_ws[OFF_H + idx] = 0.0f;
    else             g_ws[OFF_C + (idx - 65536)] = 0.0f;
}

// ---------------- cell kernel ----------------
__global__ void __launch_bounds__(256) cell_k(const float* __restrict__ XG_t, int t)
{
    int idx = blockIdx.x * 256 + threadIdx.x;
    int b = idx >> 9, h = idx & 511;
    float pre[NG];
#pragma unroll
    for (int g = 0; g < NG; g++)
        pre[g] = XG_t[(size_t)b * (TSEQ * 2560) + (size_t)g * 512 + h];
    pdl_wait();
    const float* preA  = g_ws + OFF_PREA;
    const float* preB0 = g_ws + OFF_PREB;
    const float* preB1 = g_ws + OFF_PREB + 128ull * 2560ull;
#pragma unroll
    for (int g = 0; g < NG; g++) {
        size_t col = (size_t)g * 512 + h;
        pre[g] += preA[(size_t)b * 2560 + col] + preB0[(size_t)b * 2560 + col]
                + preB1[(size_t)b * 2560 + col];
    }
    float f  = fsig(pre[0]);
    float i_ = fsig(pre[1]);
    float Tt = fsig(pre[2]);
    float zt = ftanh(pre[3]);
    float o  = fsig(pre[4]);
    float sv = g_ws[OFF_S + idx];
    float cv = f * g_ws[OFF_C + idx] + i_ * zt + Tt * sv;
    g_ws[OFF_C + idx] = cv;
    float ht = o * ftanh(cv);
    g_ws[OFF_HC + (size_t)b * 1024 + h]       = ht;
    g_ws[OFF_HC + (size_t)b * 1024 + 512 + h] = cv;
    g_ws[OFF_HE + (size_t)b * 1024 + h]       = ht;
}

// ---------------- attention kernel: 512 threads (16 warps) ----------------
__global__ void __launch_bounds__(512) attn_k(
    const float* __restrict__ ba, const float* __restrict__ vt, int t)
{
    __shared__ float qv[512];
    __shared__ float sc[32];
    __shared__ float al[32];
    int b = blockIdx.x, tid = threadIdx.x;
    float ba0 = ba[tid];                 // static prefetch (1/thread)
    pdl_wait();
    float* he = g_ws + OFF_HE;
    if (t == 0) {
        he[(size_t)b * 1024 + 512 + tid] = 0.0f;
        return;
    }
    int nv = (t < MWIN) ? t : MWIN;
    const float* qs  = g_ws + OFF_QS;
    const float* P   = g_ws + OFF_P;
    const float* buf = g_ws + OFF_BUF;
    {
        float q = ba0;
#pragma unroll
        for (int s = 0; s < 8; s++) q += qs[(size_t)s * 65536 + (size_t)b * 512 + tid];
        qv[tid] = q;
    }
    __syncthreads();
    int wid = tid >> 5, lane = tid & 31;
    for (int mi = wid; mi < nv; mi += 16) {
        int slot = (t - 1 - mi) & 31;
        const float* Pp = P + ((size_t)b * 32 + slot) * 512;
        float ps = 0.0f;
        for (int h = lane; h < 512; h += 32)
            ps += vt[h] * ftanh(qv[h] + Pp[h]);
#pragma unroll
        for (int o = 16; o; o >>= 1) ps += __shfl_xor_sync(0xffffffffu, ps, o);
        if (lane == 0) sc[mi] = ps;
    }
    __syncthreads();
    if (wid == 0) {
        float s = (lane < nv) ? sc[lane] : -1e30f;
        float mx = s;
#pragma unroll
        for (int o = 16; o; o >>= 1) mx = fmaxf(mx, __shfl_xor_sync(0xffffffffu, mx, o));
        float e = (lane < nv) ? __expf(s - mx) : 0.0f;
        float sum = e;
#pragma unroll
        for (int o = 16; o; o >>= 1) sum += __shfl_xor_sync(0xffffffffu, sum, o);
        al[lane] = __fdividef(e, sum);
    }
    __syncthreads();
    {
        float e = 0.0f;
        for (int mi = 0; mi < nv; mi++) {
            int slot = (t - 1 - mi) & 31;
            e = fmaf(al[mi], buf[((size_t)b * 32 + slot) * 512 + tid], e);
        }
        he[(size_t)b * 1024 + 512 + tid] = e;
    }
}

// ---------------- h update + logit + next-step L2 prefetch ----------------
__global__ void __launch_bounds__(512) hout_k(
    const float* __restrict__ GP_t,
    const float* __restrict__ Wcls, const float* __restrict__ bcls,
    float* __restrict__ out, int t,
    const float* __restrict__ xg_next,
    const float* __restrict__ gp_next,
    const float* __restrict__ xs_next)
{
    int b = blockIdx.x, h = threadIdx.x;
    float pre = GP_t[(size_t)b * (TSEQ * HID) + h];
    float wc  = Wcls[h];

    if (h < 80)
        l2pf(xg_next + (size_t)b * (TSEQ * 2560) + h * 32);
    else if (h < 96)
        l2pf(gp_next + (size_t)b * (TSEQ * HID) + (h - 80) * 32);
    else if (h < 112)
        l2pf(xs_next + (size_t)b * (TSEQ * HID) + (h - 96) * 32);

    pdl_wait();
    const float* hs = g_ws + OFF_HS;
#pragma unroll
    for (int s = 0; s < 8; s++) pre += hs[(size_t)s * 65536 + (size_t)b * 512 + h];
    float ht = ftanh(pre);
    g_ws[OFF_H + (size_t)b * 512 + h] = ht;
    g_ws[OFF_BUF + ((size_t)b * 32 + (t & 31)) * 512 + h] = ht;

    float p = ht * wc;
#pragma unroll
    for (int o = 16; o; o >>= 1) p += __shfl_xor_sync(0xffffffffu, p, o);
    __shared__ float red[16];
    int wid = h >> 5, lane = h & 31;
    if (lane == 0) red[wid] = p;
    __syncthreads();
    if (wid == 0) {
        float p2 = (lane < 16) ? red[lane] : 0.0f;
#pragma unroll
        for (int o = 8; o; o >>= 1) p2 += __shfl_xor_sync(0xffffffffu, p2, o);
        if (lane == 0) out[(size_t)b * TSEQ + t] = p2 + bcls[0];
    }
}

// ---------------- PDL launch helper ----------------
template<typename Kern, typename... Args>
static inline void pdl(Kern kern, dim3 g, dim3 b, Args... args)
{
    cudaLaunchConfig_t cfg = {};
    cfg.gridDim = g;
    cfg.blockDim = b;
    cfg.dynamicSmemBytes = 0;
    cfg.stream = 0;
    cudaLaunchAttribute at;
    at.id = cudaLaunchAttributeProgrammaticStreamSerialization;
    at.val.programmaticStreamSerializationAllowed = 1;
    cfg.attrs = &at;
    cfg.numAttrs = 1;
    cudaLaunchKernelEx(&cfg, kern, args...);
}

// ---------------- host ----------------
extern "C" void kernel_launch(void* const* d_in, const int* in_sizes, int n_in,
                              void* d_out, int out_size)
{
    const float* x    = (const float*)d_in[0];
    const float* dlt  = (const float*)d_in[1];
    const float* gseq = (const float*)d_in[2];
    const float* Wsh  = (const float*)d_in[3];
    const float* Wsx  = (const float*)d_in[4];
    const float* Wst  = (const float*)d_in[5];
    const float* bs   = (const float*)d_in[6];
    const float* Wh5  = (const float*)d_in[7];
    const float* Wx5  = (const float*)d_in[8];
    const float* Ws5  = (const float*)d_in[9];
    const float* bg   = (const float*)d_in[10];
    const float* Waq  = (const float*)d_in[11];
    const float* Wah  = (const float*)d_in[12];
    const float* ba   = (const float*)d_in[13];
    const float* vt   = (const float*)d_in[14];
    const float* W_h  = (const float*)d_in[15];
    const float* W_e  = (const float*)d_in[16];
    const float* W_g  = (const float*)d_in[17];
    const float* b_h  = (const float*)d_in[18];
    const float* Wcls = (const float*)d_in[19];
    const float* bcls = (const float*)d_in[20];
    float* out = (float*)d_out;

    float* ws = nullptr;
    cudaGetSymbolAddress((void**)&ws, g_ws);

    auto launchA = [&](int t) {
        int slotp = (t + 31) & 31;
        pdl(gemm2_k<3>, dim3(NA / 64, 2, 1), dim3(512),
            (const float*)(ws + OFF_H), HID,
            (const float*)(ws + OFF_WA), NA, HID,
            (float*)nullptr, 0,
            (const float*)(ws + OFF_XS + (size_t)t * HID),
            ws + OFF_S, ws + OFF_PREA, ws + OFF_P + (size_t)slotp * HID);
    };
    auto launchB = [&]() {
        pdl(gemm2_k<0>, dim3(NB / 64, 2, 2), dim3(512),
            (const float*)(ws + OFF_S), HID,
            (const float*)(ws + OFF_WB), NB, HID / 2,
            ws + OFF_PREB, NB,
            (const float*)nullptr, (float*)nullptr, (float*)nullptr, (float*)nullptr);
    };
    auto launchC = [&]() {
        pdl(gemm_k<0>, dim3(HID / 64, 2, 8), dim3(256),
            (const float*)(ws + OFF_HC), 1024, Waq, HID, 1024 / 8,
            ws + OFF_QS, HID,
            (const float*)nullptr, (const float*)nullptr, (const float*)nullptr);
    };
    auto launchD = [&]() {
        pdl(gemm_k<0>, dim3(HID / 64, 2, 8), dim3(256),
            (const float*)(ws + OFF_HE), 1024,
            (const float*)(ws + OFF_WD), HID, 1024 / 8,
            ws + OFF_HS, HID,
            (const float*)nullptr, (const float*)nullptr, (const float*)nullptr);
    };
    auto launchH = [&](int t) {
        int tn = (t + 1 < TSEQ) ? t + 1 : 0;
        pdl(hout_k, dim3(128), dim3(512),
            (const float*)(ws + OFF_GP + (size_t)t * HID), Wcls, bcls, out, t,
            (const float*)(ws + OFF_XG + (size_t)tn * NB),
            (const float*)(ws + OFF_GP + (size_t)tn * HID),
            (const float*)(ws + OFF_XS + (size_t)tn * HID));
    };

    // prologue interleaved with step 0 (ncu -s 5 catches step-0 GEMM A)
    pdl(zero_hc_k, dim3(512), dim3(256));                                    // 1
    pdl(packA_k, dim3((512 * NA) / 256), dim3(256), Wsh, Wh5, Wah);          // 2
    pdl(gemm_k<2>, dim3(8, 256, 1), dim3(256),                               // 3: XS
        x, DIN, Wsx, HID, DIN, ws + OFF_XS, HID, bs, Wst, dlt);
    launchA(0);                                                              // 4
    pdl(packB_k, dim3((512 * NB) / 256), dim3(256), Ws5);                    // 5
    launchB();                                                               // 6
    pdl(packXG_k, dim3((128 * NB) / 256), dim3(256), Wx5);                   // 7
    pdl(gemm_k<1>, dim3(40, 256, 1), dim3(256),                              // 8: XG
        x, DIN, (const float*)(ws + OFF_WXG), NB, DIN,
        ws + OFF_XG, NB, bg, (const float*)nullptr, (const float*)nullptr);
    pdl(cell_k, dim3(256), dim3(256), (const float*)(ws + OFF_XG), 0);       // 9
    launchC();                                                               // 10
    pdl(attn_k, dim3(128), dim3(512), ba, vt, 0);                            // 11
    pdl(packD_k, dim3((1024 * 512) / 256), dim3(256), W_h, W_e);             // 12
    launchD();                                                               // 13
    pdl(gemm_k<1>, dim3(8, 256, 1), dim3(256),                               // 14: GP
        gseq, DIN, W_g, HID, DIN,
        ws + OFF_GP, HID, b_h, (const float*)nullptr, (const float*)nullptr);
    launchH(0);                                                              // 15

    for (int t = 1; t < TSEQ; t++) {
        launchA(t);
        launchB();
        pdl(cell_k, dim3(256), dim3(256),
            (const float*)(ws + OFF_XG + (size_t)t * NB), t);
        launchC();
        pdl(attn_k, dim3(128), dim3(512), ba, vt, t);
        launchD();
        launchH(t);
    }
    (void)in_sizes; (void)n_in; (void)out_size;
}